// round 2
// baseline (speedup 1.0000x reference)
#include <cuda_runtime.h>
#include <math.h>

#define BATCH 64
#define SEQ   512
#define EMBD  128
#define HID   256
#define H4    1024
#define TAGS  9
#define NBLK  128   // LSTM grid blocks (must all be co-resident; 128 <= 148 SMs)

// ---------------- scratch (static device globals; no allocation) ----------------
__device__ float g_xz[2u * SEQ * H4 * BATCH];          // [dir][t][col][b]  256 MB
__device__ float g_h[(size_t)BATCH * SEQ * 2 * HID];   // [b][t][512]        64 MB
__device__ float g_hstate[2 * 2 * HID * BATCH];        // [buf][dir][u][b]
__device__ int   g_lens[BATCH];
__device__ float g_score[BATCH];
__device__ float g_norm[BATCH];
__device__ volatile unsigned g_flags[NBLK];
__device__ volatile unsigned g_gen;

// ---------------- replay-safe software grid barrier ----------------
// flags/g_gen are zeroed by init_kernel at the start of every kernel_launch,
// so absolute step numbers (1..512) are safe across graph replays.
__device__ __forceinline__ void grid_barrier(unsigned bstep) {
    __syncthreads();
    if (threadIdx.x == 0) {
        __threadfence();
        g_flags[blockIdx.x] = bstep;
    }
    if (blockIdx.x == 0) {
        if (threadIdx.x < NBLK) {
            while (g_flags[threadIdx.x] < bstep) { }
        }
        __syncthreads();
        if (threadIdx.x == 0) {
            __threadfence();
            g_gen = bstep;
        }
    } else {
        if (threadIdx.x == 0) {
            while (g_gen < bstep) { }
        }
    }
    __syncthreads();
}

// ---------------- init: reset barrier state + zero h0 ----------------
__global__ void init_kernel() {
    int tid = threadIdx.x;
    if (tid < NBLK) g_flags[tid] = 0;
    if (tid == 0) g_gen = 0;
    // zero buf0 state for both dirs: first 2*HID*BATCH floats
    for (int i = tid; i < 2 * HID * BATCH; i += 256) g_hstate[i] = 0.f;
}

// ---------------- text lengths ----------------
__global__ void lens_kernel(const int* __restrict__ text) {
    __shared__ int red[256];
    int b = blockIdx.x, tid = threadIdx.x;
    int c = 0;
    for (int t = tid; t < SEQ; t += 256) c += (text[b * SEQ + t] != 0);
    red[tid] = c;
    __syncthreads();
    for (int o = 128; o > 0; o >>= 1) {
        if (tid < o) red[tid] += red[tid + o];
        __syncthreads();
    }
    if (tid == 0) g_lens[b] = red[0];
}

// ---------------- input GEMM: xz[dir][s][col][b] = emb[text[b,s]] @ W + bias ----------------
// grid: (32 colchunks [0..15]->fwd, [16..31]->bwd, 512 s), 256 threads, 64x64 tile, K=128 in 2 chunks
__global__ void gemm_kernel(const int* __restrict__ text, const float* __restrict__ emb,
                            const float* __restrict__ W_f, const float* __restrict__ b_f,
                            const float* __restrict__ W_b, const float* __restrict__ b_b) {
    __shared__ float Ash[64][64];   // [k][b]
    __shared__ float Wsh[64][64];   // [k][c]
    __shared__ int tok[64];
    int tid = threadIdx.x;
    int cc = blockIdx.x, s = blockIdx.y;
    int dir = cc >> 4;
    int c0 = (cc & 15) * 64;
    const float* W    = dir ? W_b : W_f;
    const float* bias = dir ? b_b : b_f;
    if (tid < 64) tok[tid] = text[tid * SEQ + s];
    __syncthreads();

    int tx = tid & 15;   // b group: b = tx*4 + bi
    int ty = tid >> 4;   // c group: c = ty*4 + cj
    float acc[4][4];
#pragma unroll
    for (int i = 0; i < 4; i++)
#pragma unroll
        for (int j = 0; j < 4; j++) acc[i][j] = 0.f;

    for (int kc = 0; kc < 2; kc++) {
        // load A tile (gathered embedding rows), stored transposed [k][b]
        {
            int bb = tid >> 2, p = tid & 3;
            const float4* src = (const float4*)(emb + (size_t)tok[bb] * EMBD + kc * 64 + p * 16);
            float4 v0 = src[0], v1 = src[1], v2 = src[2], v3 = src[3];
            int kb = p * 16;
            Ash[kb + 0][bb] = v0.x;  Ash[kb + 1][bb] = v0.y;  Ash[kb + 2][bb] = v0.z;  Ash[kb + 3][bb] = v0.w;
            Ash[kb + 4][bb] = v1.x;  Ash[kb + 5][bb] = v1.y;  Ash[kb + 6][bb] = v1.z;  Ash[kb + 7][bb] = v1.w;
            Ash[kb + 8][bb] = v2.x;  Ash[kb + 9][bb] = v2.y;  Ash[kb +10][bb] = v2.z;  Ash[kb +11][bb] = v2.w;
            Ash[kb +12][bb] = v3.x;  Ash[kb +13][bb] = v3.y;  Ash[kb +14][bb] = v3.z;  Ash[kb +15][bb] = v3.w;
        }
        // load W tile
        for (int i = tid; i < 1024; i += 256) {
            int k = i >> 4, c4 = i & 15;
            ((float4*)&Wsh[k][0])[c4] = *(const float4*)(W + (size_t)(kc * 64 + k) * H4 + c0 + c4 * 4);
        }
        __syncthreads();
#pragma unroll 8
        for (int k = 0; k < 64; k++) {
            float4 av = *(const float4*)&Ash[k][tx * 4];
            float4 wv = *(const float4*)&Wsh[k][ty * 4];
            acc[0][0] += av.x * wv.x;  acc[0][1] += av.x * wv.y;  acc[0][2] += av.x * wv.z;  acc[0][3] += av.x * wv.w;
            acc[1][0] += av.y * wv.x;  acc[1][1] += av.y * wv.y;  acc[1][2] += av.y * wv.z;  acc[1][3] += av.y * wv.w;
            acc[2][0] += av.z * wv.x;  acc[2][1] += av.z * wv.y;  acc[2][2] += av.z * wv.z;  acc[2][3] += av.z * wv.w;
            acc[3][0] += av.w * wv.x;  acc[3][1] += av.w * wv.y;  acc[3][2] += av.w * wv.z;  acc[3][3] += av.w * wv.w;
        }
        __syncthreads();
    }
    // epilogue: + bias, store to g_xz [dir][s][col][b]
    float* dst = g_xz + ((size_t)(dir * SEQ + s) * H4) * BATCH;
#pragma unroll
    for (int j = 0; j < 4; j++) {
        int col = c0 + ty * 4 + j;
        float bv = bias[col];
        float4 o;
        o.x = acc[0][j] + bv;  o.y = acc[1][j] + bv;  o.z = acc[2][j] + bv;  o.w = acc[3][j] + bv;
        *(float4*)(dst + (size_t)col * BATCH + tx * 4) = o;
    }
}

// ---------------- LSTM recurrence (both directions), persistent grid-synced kernel ----------------
// 128 blocks: blockIdx = dir*64 + cb; block handles hidden units [cb*4, cb*4+4) for all 64 batches.
// U columns (16 per block) preloaded to shared once. h staged to shared per step. c in a register.
__global__ void lstm_kernel(const float* __restrict__ U_f, const float* __restrict__ U_b) {
    extern __shared__ float sm[];
    float* Ush = sm;          // [256][16] : [k][ul*4+gate]
    float* hsh = sm + 4096;   // [256][64] : [k][b]
    int tid = threadIdx.x;
    int dir = blockIdx.x >> 6;
    int cb  = blockIdx.x & 63;
    int u0 = cb * 4;
    const float* U = dir ? U_b : U_f;
    for (int i = tid; i < 4096; i += 256) {
        int k = i >> 4, c = i & 15;
        int ul2 = c >> 2, gg = c & 3;
        Ush[i] = U[(size_t)k * H4 + gg * HID + u0 + ul2];
    }
    int b = tid & 63, ul = tid >> 6;
    int u = u0 + ul;
    float c_reg = 0.f;
    __syncthreads();

    for (int ti = 0; ti < SEQ; ti++) {
        int buf = ti & 1;
        int t = dir ? (SEQ - 1 - ti) : ti;
        // stage h (from other blocks; bypass L1 for coherence)
        {
            const float4* hs = (const float4*)(g_hstate + (buf * 2 + dir) * (HID * BATCH));
            float4* hd = (float4*)hsh;
            for (int i = tid; i < HID * BATCH / 4; i += 256) hd[i] = __ldcg(hs + i);
        }
        __syncthreads();

        float a0 = 0.f, a1 = 0.f, a2 = 0.f, a3 = 0.f;
        const float* up = Ush + ul * 4;
#pragma unroll 8
        for (int k = 0; k < HID; k++) {
            float hv = hsh[k * 64 + b];
            float4 uv = *(const float4*)(up + k * 16);
            a0 += hv * uv.x;  a1 += hv * uv.y;  a2 += hv * uv.z;  a3 += hv * uv.w;
        }
        const float* xzp = g_xz + ((size_t)(dir * SEQ + t) * H4) * BATCH;
        float zi = xzp[(0 * HID + u) * BATCH + b] + a0;
        float zf = xzp[(1 * HID + u) * BATCH + b] + a1;
        float zg = xzp[(2 * HID + u) * BATCH + b] + a2;
        float zo = xzp[(3 * HID + u) * BATCH + b] + a3;
        float ig = 1.f / (1.f + expf(-zi));
        float fg = 1.f / (1.f + expf(-zf));
        float gv = tanhf(zg);
        float og = 1.f / (1.f + expf(-zo));
        c_reg = fg * c_reg + ig * gv;
        float hv = og * tanhf(c_reg);
        __stcg(g_hstate + ((buf ^ 1) * 2 + dir) * (HID * BATCH) + u * BATCH + b, hv);
        g_h[((size_t)b * SEQ + t) * (2 * HID) + dir * HID + u] = hv;
        grid_barrier((unsigned)(ti + 1));
    }
}

// ---------------- decoder: logits = h @ W_d + b_d ----------------
__global__ void decoder_kernel(const float* __restrict__ W_d, const float* __restrict__ b_d,
                               float* __restrict__ out) {
    __shared__ float Wd[512 * TAGS];
    __shared__ float bd[TAGS];
    int tid = threadIdx.x;
    for (int i = tid; i < 512 * TAGS; i += 256) Wd[i] = W_d[i];
    if (tid < TAGS) bd[tid] = b_d[tid];
    __syncthreads();
    int w = tid >> 5, lane = tid & 31;
    for (int rr = 0; rr < 8; rr++) {
        int r = blockIdx.x * 64 + w * 8 + rr;
        float acc[TAGS];
#pragma unroll
        for (int t = 0; t < TAGS; t++) acc[t] = 0.f;
        const float* hp = g_h + (size_t)r * 512;
        for (int k = lane; k < 512; k += 32) {
            float hv = hp[k];
#pragma unroll
            for (int t = 0; t < TAGS; t++) acc[t] += hv * Wd[k * TAGS + t];
        }
#pragma unroll
        for (int t = 0; t < TAGS; t++)
            for (int o = 16; o > 0; o >>= 1) acc[t] += __shfl_down_sync(0xffffffffu, acc[t], o);
        if (lane == 0) {
#pragma unroll
            for (int t = 0; t < TAGS; t++) out[(size_t)r * TAGS + t] = acc[t] + bd[t];
        }
    }
}

// ---------------- CRF log-normalizer (forward algorithm), one warp per batch ----------------
__global__ void crf_fwd_kernel(const float* __restrict__ trans, const float* __restrict__ logits) {
    int b = blockIdx.x, j = threadIdx.x;
    __shared__ float ash[TAGS];
    float tcol[TAGS];
    if (j < TAGS) {
#pragma unroll
        for (int i = 0; i < TAGS; i++) tcol[i] = trans[i * TAGS + j];
    }
    float alpha = (j < TAGS) ? logits[(size_t)b * SEQ * TAGS + j] : -1e30f;
    int len = g_lens[b];
    for (int t = 1; t < SEQ; t++) {
        if (j < TAGS) ash[j] = alpha;
        __syncwarp();
        if (j < TAGS) {
            float m = -1e30f;
#pragma unroll
            for (int i = 0; i < TAGS; i++) m = fmaxf(m, ash[i] + tcol[i]);
            float sum = 0.f;
#pragma unroll
            for (int i = 0; i < TAGS; i++) sum += expf(ash[i] + tcol[i] - m);
            float nv = m + logf(sum) + logits[((size_t)b * SEQ + t) * TAGS + j];
            if (t < len) alpha = nv;
        }
        __syncwarp();
    }
    if (j < TAGS) ash[j] = alpha;
    __syncwarp();
    if (j == 0) {
        float m = -1e30f;
#pragma unroll
        for (int i = 0; i < TAGS; i++) m = fmaxf(m, ash[i]);
        float s = 0.f;
#pragma unroll
        for (int i = 0; i < TAGS; i++) s += expf(ash[i] - m);
        g_norm[b] = m + logf(s);
    }
}

// ---------------- CRF gold-path score ----------------
__global__ void crf_score_kernel(const int* __restrict__ labels, const float* __restrict__ trans,
                                 const float* __restrict__ logits) {
    __shared__ float red[128];
    int b = blockIdx.x, tid = threadIdx.x;
    int len = g_lens[b];
    float sc = 0.f;
    for (int t = tid; t < SEQ; t += 128) {
        int lab = labels[b * SEQ + t];
        if (t < len) sc += logits[((size_t)b * SEQ + t) * TAGS + lab];
        if (t < SEQ - 1 && t < len - 1) sc += trans[lab * TAGS + labels[b * SEQ + t + 1]];
    }
    red[tid] = sc;
    __syncthreads();
    for (int o = 64; o > 0; o >>= 1) {
        if (tid < o) red[tid] += red[tid + o];
        __syncthreads();
    }
    if (tid == 0) g_score[b] = red[0];
}

// ---------------- finalize: lens (as float) + log_likelihood ----------------
__global__ void final_kernel(float* __restrict__ out) {
    int i = threadIdx.x;
    if (i < BATCH) {
        out[BATCH * SEQ * TAGS + i] = (float)g_lens[i];
        out[BATCH * SEQ * TAGS + BATCH + i] = g_score[i] - g_norm[i];
    }
}

// ---------------- launch ----------------
extern "C" void kernel_launch(void* const* d_in, const int* in_sizes, int n_in,
                              void* d_out, int out_size) {
    const int*   text   = (const int*)d_in[0];
    const int*   labels = (const int*)d_in[1];
    const float* emb    = (const float*)d_in[2];
    const float* W_f    = (const float*)d_in[3];
    const float* U_f    = (const float*)d_in[4];
    const float* b_f    = (const float*)d_in[5];
    const float* W_b    = (const float*)d_in[6];
    const float* U_b    = (const float*)d_in[7];
    const float* b_b    = (const float*)d_in[8];
    const float* W_d    = (const float*)d_in[9];
    const float* b_d    = (const float*)d_in[10];
    const float* trans  = (const float*)d_in[11];
    float* out = (float*)d_out;

    cudaFuncSetAttribute(lstm_kernel, cudaFuncAttributeMaxDynamicSharedMemorySize, 81920);

    lens_kernel<<<BATCH, 256>>>(text);
    gemm_kernel<<<dim3(32, SEQ), 256>>>(text, emb, W_f, b_f, W_b, b_b);
    init_kernel<<<1, 256>>>();
    lstm_kernel<<<NBLK, 256, 81920>>>(U_f, U_b);
    decoder_kernel<<<512, 256>>>(W_d, b_d, out);
    crf_fwd_kernel<<<BATCH, 32>>>(trans, out);
    crf_score_kernel<<<BATCH, 128>>>(labels, trans, out);
    final_kernel<<<1, 64>>>(out);
}

// round 3
// speedup vs baseline: 1.1737x; 1.1737x over previous
#include <cuda_runtime.h>
#include <math.h>

#define BATCH 64
#define SEQ   512
#define EMBD  128
#define HID   256
#define H4    1024
#define TAGS  9
#define NBLK  128   // LSTM grid blocks (all co-resident; 128 <= 148 SMs, 1 per SM)

// ---------------- scratch (static device globals; no allocation) ----------------
__device__ float g_xz[2u * SEQ * H4 * BATCH];          // [dir][t][col][b]
__device__ float g_h[(size_t)BATCH * SEQ * 2 * HID];   // [b][t][512]
__device__ float g_hstate[2 * 2 * HID * BATCH];        // [buf][dir][u][b]
__device__ int   g_lens[BATCH];
__device__ float g_score[BATCH];
__device__ float g_norm[BATCH];
__device__ unsigned g_count;
__device__ volatile unsigned g_gen;

// ---------------- f32x2 helpers ----------------
__device__ __forceinline__ void fma2(unsigned long long& d, unsigned long long a, unsigned long long b) {
    asm("fma.rn.f32x2 %0, %1, %2, %0;" : "+l"(d) : "l"(a), "l"(b));
}
__device__ __forceinline__ void add2(unsigned long long& d, unsigned long long a) {
    asm("add.rn.f32x2 %0, %0, %1;" : "+l"(d) : "l"(a));
}
__device__ __forceinline__ unsigned long long pk2(float a) {
    unsigned long long d;
    asm("mov.b64 %0, {%1, %1};" : "=l"(d) : "f"(a));
    return d;
}
__device__ __forceinline__ float2 up2(unsigned long long v) {
    float2 r;
    r.x = __uint_as_float((unsigned)v);
    r.y = __uint_as_float((unsigned)(v >> 32));
    return r;
}
__device__ __forceinline__ float sigf(float x) { return __fdividef(1.f, 1.f + __expf(-x)); }
__device__ __forceinline__ float tanf2(float x) { return __fdividef(2.f, 1.f + __expf(-2.f * x)) - 1.f; }

// ---------------- replay-safe software grid barrier (single atomic arrive) ----------------
__device__ __forceinline__ void grid_barrier(unsigned step) {
    __syncthreads();
    if (threadIdx.x == 0) {
        __threadfence();
        unsigned prev = atomicAdd(&g_count, 1u);
        if (prev == step * NBLK - 1u) {
            __threadfence();
            g_gen = step;
        } else {
            while (g_gen < step) { }
            __threadfence();
        }
    }
    __syncthreads();
}

// ---------------- init: reset barrier state + zero h0 ----------------
__global__ void init_kernel() {
    int tid = threadIdx.x;
    if (tid == 0) { g_count = 0; g_gen = 0; }
    for (int i = tid; i < 2 * HID * BATCH; i += 256) g_hstate[i] = 0.f;
}

// ---------------- text lengths ----------------
__global__ void lens_kernel(const int* __restrict__ text) {
    __shared__ int red[256];
    int b = blockIdx.x, tid = threadIdx.x;
    int c = 0;
    for (int t = tid; t < SEQ; t += 256) c += (text[b * SEQ + t] != 0);
    red[tid] = c;
    __syncthreads();
    for (int o = 128; o > 0; o >>= 1) {
        if (tid < o) red[tid] += red[tid + o];
        __syncthreads();
    }
    if (tid == 0) g_lens[b] = red[0];
}

// ---------------- input GEMM: xz[dir][s][col][b] = emb[text[b,s]] @ W + bias (f32x2) ----------------
__global__ void gemm_kernel(const int* __restrict__ text, const float* __restrict__ emb,
                            const float* __restrict__ W_f, const float* __restrict__ b_f,
                            const float* __restrict__ W_b, const float* __restrict__ b_b) {
    __shared__ float Ash[64][64];   // [k][b]
    __shared__ float Wsh[64][64];   // [k][c]
    __shared__ int tok[64];
    int tid = threadIdx.x;
    int cc = blockIdx.x, s = blockIdx.y;
    int dir = cc >> 4;
    int c0 = (cc & 15) * 64;
    const float* W    = dir ? W_b : W_f;
    const float* bias = dir ? b_b : b_f;
    if (tid < 64) tok[tid] = text[tid * SEQ + s];
    __syncthreads();

    int tx = tid & 15;   // b group
    int ty = tid >> 4;   // c group
    unsigned long long acc2[4][2];
#pragma unroll
    for (int i = 0; i < 4; i++) { acc2[i][0] = 0ull; acc2[i][1] = 0ull; }

    for (int kc = 0; kc < 2; kc++) {
        {
            int bb = tid >> 2, pp = tid & 3;
            const float4* src = (const float4*)(emb + (size_t)tok[bb] * EMBD + kc * 64 + pp * 16);
            float4 v0 = src[0], v1 = src[1], v2 = src[2], v3 = src[3];
            int kb = pp * 16;
            Ash[kb + 0][bb] = v0.x;  Ash[kb + 1][bb] = v0.y;  Ash[kb + 2][bb] = v0.z;  Ash[kb + 3][bb] = v0.w;
            Ash[kb + 4][bb] = v1.x;  Ash[kb + 5][bb] = v1.y;  Ash[kb + 6][bb] = v1.z;  Ash[kb + 7][bb] = v1.w;
            Ash[kb + 8][bb] = v2.x;  Ash[kb + 9][bb] = v2.y;  Ash[kb +10][bb] = v2.z;  Ash[kb +11][bb] = v2.w;
            Ash[kb +12][bb] = v3.x;  Ash[kb +13][bb] = v3.y;  Ash[kb +14][bb] = v3.z;  Ash[kb +15][bb] = v3.w;
        }
        for (int i = tid; i < 1024; i += 256) {
            int k = i >> 4, c4 = i & 15;
            ((float4*)&Wsh[k][0])[c4] = *(const float4*)(W + (size_t)(kc * 64 + k) * H4 + c0 + c4 * 4);
        }
        __syncthreads();
#pragma unroll 8
        for (int k = 0; k < 64; k++) {
            float4 av = *(const float4*)&Ash[k][tx * 4];
            ulonglong2 wv = *(const ulonglong2*)&Wsh[k][ty * 4];
            unsigned long long d0 = pk2(av.x), d1 = pk2(av.y), d2 = pk2(av.z), d3 = pk2(av.w);
            fma2(acc2[0][0], d0, wv.x);  fma2(acc2[0][1], d0, wv.y);
            fma2(acc2[1][0], d1, wv.x);  fma2(acc2[1][1], d1, wv.y);
            fma2(acc2[2][0], d2, wv.x);  fma2(acc2[2][1], d2, wv.y);
            fma2(acc2[3][0], d3, wv.x);  fma2(acc2[3][1], d3, wv.y);
        }
        __syncthreads();
    }
    float accf[4][4];
#pragma unroll
    for (int i = 0; i < 4; i++) {
        float2 t0 = up2(acc2[i][0]), t1 = up2(acc2[i][1]);
        accf[i][0] = t0.x; accf[i][1] = t0.y; accf[i][2] = t1.x; accf[i][3] = t1.y;
    }
    float* dst = g_xz + ((size_t)(dir * SEQ + s) * H4) * BATCH;
#pragma unroll
    for (int j = 0; j < 4; j++) {
        int col = c0 + ty * 4 + j;
        float bv = bias[col];
        float4 o;
        o.x = accf[0][j] + bv;  o.y = accf[1][j] + bv;  o.z = accf[2][j] + bv;  o.w = accf[3][j] + bv;
        *(float4*)(dst + (size_t)col * BATCH + tx * 4) = o;
    }
}

// ---------------- LSTM recurrence: 128 blocks x 512 threads, f32x2, k-split x8 ----------------
// block = dir*64 + cb; block owns 4 hidden units (u0..u0+3), all 64 batches.
// thread: ks = tid>>6 (k chunk of 32), ulp = (tid>>5)&1 (unit pair), p = tid&31 (batch pair).
// Ush stored duplicated: [k][ul][ (ui,ui,uf,uf, ug,ug,uo,uo) ] -> f32x2 multipliers, broadcast LDS.
__global__ void __launch_bounds__(512, 1) lstm_kernel(const float* __restrict__ U_f,
                                                      const float* __restrict__ U_b) {
    extern __shared__ float sm[];
    float* Ush = sm;                       // 8192 floats  (256*4*8)
    float* hsh = sm + 8192;                // 16384 floats ([256 k][64 b])
    float* red = sm + 8192 + 16384;        // 10240 floats (8 ks * 64 * 20 stride)
    const int tid = threadIdx.x;
    const int dir = blockIdx.x >> 6;
    const int cb  = blockIdx.x & 63;
    const int u0  = cb * 4;
    const float* U = dir ? U_b : U_f;
    for (int i = tid; i < 4096; i += 512) {
        int k = i >> 4, r = i & 15, ul = r >> 2, g = r & 3;
        float v = U[(size_t)k * H4 + g * HID + u0 + ul];
        int o = (k * 4 + ul) * 8 + g * 2;
        Ush[o] = v; Ush[o + 1] = v;
    }
    const int ks  = tid >> 6;
    const int gi  = tid & 63;
    const int ulp = gi >> 5;
    const int p   = gi & 31;
    const int ue  = tid >> 5;   // epilogue unit (valid for tid<128)
    const int pe  = tid & 31;
    const float* hRow = hsh + ks * 32 * 64 + 2 * p;        // + kk*64
    const float* uRow = Ush + ks * 1024 + ulp * 16;        // + kk*32 ; 16 floats = 2 units
    float* myRed = red + (ks * 64 + gi) * 20;
    const float* eRed = red + ((ue >> 1) * 32 + pe) * 20 + (ue & 1) * 8;
    float cr0 = 0.f, cr1 = 0.f;
    __syncthreads();

    for (int ti = 0; ti < SEQ; ti++) {
        const int buf = ti & 1;
        const int t = dir ? (SEQ - 1 - ti) : ti;

        // prefetch xz for epilogue threads (independent of h)
        float2 xv0, xv1, xv2, xv3;
        if (tid < 128) {
            const float2* xzp = (const float2*)(g_xz + ((size_t)(dir * SEQ + t) * H4) * BATCH);
            int u = u0 + ue;
            xv0 = xzp[(0 * HID + u) * 32 + pe];
            xv1 = xzp[(1 * HID + u) * 32 + pe];
            xv2 = xzp[(2 * HID + u) * 32 + pe];
            xv3 = xzp[(3 * HID + u) * 32 + pe];
        }

        // stage this group's k-quarter of h (group = 64 threads, ks)
        {
            const float4* src = (const float4*)(g_hstate + (buf * 2 + dir) * (HID * BATCH) + ks * 32 * 64);
            float4* dst = (float4*)(hsh + ks * 32 * 64);
#pragma unroll
            for (int j = 0; j < 8; j++) dst[gi + 64 * j] = __ldcg(src + gi + 64 * j);
        }
        asm volatile("bar.sync %0, 64;" :: "r"(ks + 1) : "memory");

        // partial h@U over 32 k values: 2 units x 4 gates x 2 batches (f32x2 over batch pair)
        unsigned long long A00 = 0, A01 = 0, A02 = 0, A03 = 0;
        unsigned long long A10 = 0, A11 = 0, A12 = 0, A13 = 0;
#pragma unroll 4
        for (int kk = 0; kk < 32; kk++) {
            unsigned long long hv = *(const unsigned long long*)(hRow + kk * 64);
            ulonglong2 ua = *(const ulonglong2*)(uRow + kk * 32);
            ulonglong2 ub = *(const ulonglong2*)(uRow + kk * 32 + 4);
            ulonglong2 uc = *(const ulonglong2*)(uRow + kk * 32 + 8);
            ulonglong2 ud = *(const ulonglong2*)(uRow + kk * 32 + 12);
            fma2(A00, hv, ua.x);  fma2(A01, hv, ua.y);
            fma2(A02, hv, ub.x);  fma2(A03, hv, ub.y);
            fma2(A10, hv, uc.x);  fma2(A11, hv, uc.y);
            fma2(A12, hv, ud.x);  fma2(A13, hv, ud.y);
        }
        *(ulonglong2*)(myRed)      = make_ulonglong2(A00, A01);
        *(ulonglong2*)(myRed + 4)  = make_ulonglong2(A02, A03);
        *(ulonglong2*)(myRed + 8)  = make_ulonglong2(A10, A11);
        *(ulonglong2*)(myRed + 12) = make_ulonglong2(A12, A13);
        __syncthreads();

        // epilogue: 128 threads (unit ue, batches 2*pe, 2*pe+1)
        if (tid < 128) {
            unsigned long long S0 = 0, S1 = 0, S2 = 0, S3 = 0;
#pragma unroll
            for (int s = 0; s < 8; s++) {
                ulonglong2 r0 = *(const ulonglong2*)(eRed + s * 64 * 20);
                ulonglong2 r1 = *(const ulonglong2*)(eRed + s * 64 * 20 + 4);
                add2(S0, r0.x);  add2(S1, r0.y);
                add2(S2, r1.x);  add2(S3, r1.y);
            }
            float2 zi = up2(S0), zf = up2(S1), zg = up2(S2), zo = up2(S3);
            zi.x += xv0.x;  zi.y += xv0.y;
            zf.x += xv1.x;  zf.y += xv1.y;
            zg.x += xv2.x;  zg.y += xv2.y;
            zo.x += xv3.x;  zo.y += xv3.y;
            float i0 = sigf(zi.x), f0 = sigf(zf.x), g0 = tanf2(zg.x), o0 = sigf(zo.x);
            float i1 = sigf(zi.y), f1 = sigf(zf.y), g1 = tanf2(zg.y), o1 = sigf(zo.y);
            cr0 = f0 * cr0 + i0 * g0;
            cr1 = f1 * cr1 + i1 * g1;
            float h0 = o0 * tanf2(cr0);
            float h1 = o1 * tanf2(cr1);
            int u = u0 + ue;
            float* hd = g_hstate + ((buf ^ 1) * 2 + dir) * (HID * BATCH) + u * BATCH + 2 * pe;
            __stcg((float2*)hd, make_float2(h0, h1));
            size_t ob = ((size_t)(2 * pe) * SEQ + t) * (2 * HID) + dir * HID + u;
            g_h[ob] = h0;
            g_h[ob + (size_t)SEQ * 2 * HID] = h1;
        }
        grid_barrier((unsigned)(ti + 1));
    }
}

// ---------------- decoder: logits = h @ W_d + b_d ----------------
__global__ void decoder_kernel(const float* __restrict__ W_d, const float* __restrict__ b_d,
                               float* __restrict__ out) {
    __shared__ float Wd[512 * TAGS];
    __shared__ float bd[TAGS];
    int tid = threadIdx.x;
    for (int i = tid; i < 512 * TAGS; i += 256) Wd[i] = W_d[i];
    if (tid < TAGS) bd[tid] = b_d[tid];
    __syncthreads();
    int w = tid >> 5, lane = tid & 31;
    for (int rr = 0; rr < 8; rr++) {
        int r = blockIdx.x * 64 + w * 8 + rr;
        float acc[TAGS];
#pragma unroll
        for (int t = 0; t < TAGS; t++) acc[t] = 0.f;
        const float* hp = g_h + (size_t)r * 512;
        for (int k = lane; k < 512; k += 32) {
            float hv = hp[k];
#pragma unroll
            for (int t = 0; t < TAGS; t++) acc[t] += hv * Wd[k * TAGS + t];
        }
#pragma unroll
        for (int t = 0; t < TAGS; t++)
            for (int o = 16; o > 0; o >>= 1) acc[t] += __shfl_down_sync(0xffffffffu, acc[t], o);
        if (lane == 0) {
#pragma unroll
            for (int t = 0; t < TAGS; t++) out[(size_t)r * TAGS + t] = acc[t] + bd[t];
        }
    }
}

// ---------------- CRF log-normalizer ----------------
__global__ void crf_fwd_kernel(const float* __restrict__ trans, const float* __restrict__ logits) {
    int b = blockIdx.x, j = threadIdx.x;
    __shared__ float ash[TAGS];
    float tcol[TAGS];
    if (j < TAGS) {
#pragma unroll
        for (int i = 0; i < TAGS; i++) tcol[i] = trans[i * TAGS + j];
    }
    float alpha = (j < TAGS) ? logits[(size_t)b * SEQ * TAGS + j] : -1e30f;
    int len = g_lens[b];
    for (int t = 1; t < SEQ; t++) {
        if (j < TAGS) ash[j] = alpha;
        __syncwarp();
        if (j < TAGS) {
            float m = -1e30f;
#pragma unroll
            for (int i = 0; i < TAGS; i++) m = fmaxf(m, ash[i] + tcol[i]);
            float sum = 0.f;
#pragma unroll
            for (int i = 0; i < TAGS; i++) sum += expf(ash[i] + tcol[i] - m);
            float nv = m + logf(sum) + logits[((size_t)b * SEQ + t) * TAGS + j];
            if (t < len) alpha = nv;
        }
        __syncwarp();
    }
    if (j < TAGS) ash[j] = alpha;
    __syncwarp();
    if (j == 0) {
        float m = -1e30f;
#pragma unroll
        for (int i = 0; i < TAGS; i++) m = fmaxf(m, ash[i]);
        float s = 0.f;
#pragma unroll
        for (int i = 0; i < TAGS; i++) s += expf(ash[i] - m);
        g_norm[b] = m + logf(s);
    }
}

// ---------------- CRF gold-path score ----------------
__global__ void crf_score_kernel(const int* __restrict__ labels, const float* __restrict__ trans,
                                 const float* __restrict__ logits) {
    __shared__ float red[128];
    int b = blockIdx.x, tid = threadIdx.x;
    int len = g_lens[b];
    float sc = 0.f;
    for (int t = tid; t < SEQ; t += 128) {
        int lab = labels[b * SEQ + t];
        if (t < len) sc += logits[((size_t)b * SEQ + t) * TAGS + lab];
        if (t < SEQ - 1 && t < len - 1) sc += trans[lab * TAGS + labels[b * SEQ + t + 1]];
    }
    red[tid] = sc;
    __syncthreads();
    for (int o = 64; o > 0; o >>= 1) {
        if (tid < o) red[tid] += red[tid + o];
        __syncthreads();
    }
    if (tid == 0) g_score[b] = red[0];
}

// ---------------- finalize ----------------
__global__ void final_kernel(float* __restrict__ out) {
    int i = threadIdx.x;
    if (i < BATCH) {
        out[BATCH * SEQ * TAGS + i] = (float)g_lens[i];
        out[BATCH * SEQ * TAGS + BATCH + i] = g_score[i] - g_norm[i];
    }
}

// ---------------- launch ----------------
extern "C" void kernel_launch(void* const* d_in, const int* in_sizes, int n_in,
                              void* d_out, int out_size) {
    const int*   text   = (const int*)d_in[0];
    const int*   labels = (const int*)d_in[1];
    const float* emb    = (const float*)d_in[2];
    const float* W_f    = (const float*)d_in[3];
    const float* U_f    = (const float*)d_in[4];
    const float* b_f    = (const float*)d_in[5];
    const float* W_b    = (const float*)d_in[6];
    const float* U_b    = (const float*)d_in[7];
    const float* b_b    = (const float*)d_in[8];
    const float* W_d    = (const float*)d_in[9];
    const float* b_d    = (const float*)d_in[10];
    const float* trans  = (const float*)d_in[11];
    float* out = (float*)d_out;

    cudaFuncSetAttribute(lstm_kernel, cudaFuncAttributeMaxDynamicSharedMemorySize, 139264);

    lens_kernel<<<BATCH, 256>>>(text);
    gemm_kernel<<<dim3(32, SEQ), 256>>>(text, emb, W_f, b_f, W_b, b_b);
    init_kernel<<<1, 256>>>();
    lstm_kernel<<<NBLK, 512, 139264>>>(U_f, U_b);
    decoder_kernel<<<512, 256>>>(W_d, b_d, out);
    crf_fwd_kernel<<<BATCH, 32>>>(trans, out);
    crf_score_kernel<<<BATCH, 128>>>(labels, trans, out);
    final_kernel<<<1, 64>>>(out);
}